// round 4
// baseline (speedup 1.0000x reference)
#include <cuda_runtime.h>
#include <cuda_bf16.h>
#include <math.h>

// ---------------- problem constants ----------------
#define NN    8192
#define EE    262144
#define INC   64
#define OUTC  64
#define GG    64
#define NC    10
#define DIN   192      // IN_C*K
#define DOUT  192      // OUT_C*K
#define D3    576      // DOUT*3
#define D2    384      // DOUT*2
#define BNEPS 1e-5f

// ---------------- device scratch ----------------
__device__ int   g_flags[2];
__device__ int   g_deg[NN];
__device__ float g_dinv[NN];
__device__ int   g_offs[NN + 1];
__device__ int   g_cnt[NN];
__device__ int   g_col[EE];
__device__ float g_Hcat[NN * DIN];
__device__ float g_H[NN * DOUT];
__device__ float g_Wm[DOUT * DIN];
__device__ float g_bnsum[DOUT];
__device__ float g_bnsq[DOUT];
__device__ int   g_seg[GG + 1];
__device__ float g_Hg[GG * D3];

__device__ __forceinline__ int fetch_idx(const void* p, long long i, int is32) {
    if (is32) return ((const int*)p)[i];
    return (int)(((const long long*)p)[i]);
}

// ---------------- K1: init (zero + dtype flags + segment boundaries) ----------------
__global__ void init_kernel(const void* ei, const void* batch) {
    int tid = blockIdx.x * blockDim.x + threadIdx.x;
    for (int i = tid; i < NN; i += gridDim.x * blockDim.x) { g_deg[i] = 0; g_cnt[i] = 0; }
    for (int i = tid; i < DOUT; i += gridDim.x * blockDim.x) { g_bnsum[i] = 0.f; g_bnsq[i] = 0.f; }
    if (blockIdx.x == 0) {
        if (threadIdx.x == 0) {
            // int32-vs-int64 detection via high words of spread probes
            const int* e32 = (const int*)ei;
            int is32_e = 0;
            for (int k = 0; k < 64; k++) {
                long long pe = (long long)k * (EE / 64);
                if (e32[2 * pe + 1] != 0) { is32_e = 1; break; }
            }
            g_flags[0] = is32_e;
            const int* b32p = (const int*)batch;
            int is32_b = 0;
            for (int k = 0; k < 64; k++) {
                long long pb = (long long)k * (NN / 128);
                if (b32p[2 * pb + 1] != 0) { is32_b = 1; break; }
            }
            g_flags[1] = is32_b;
        }
        __syncthreads();
        int g = threadIdx.x;
        if (g <= GG) {
            if (g == GG) { g_seg[GG] = NN; }
            else {
                int is32 = g_flags[1];
                int lo = 0, hi = NN;
                while (lo < hi) {
                    int mid = (lo + hi) >> 1;
                    if (fetch_idx(batch, mid, is32) < g) lo = mid + 1; else hi = mid;
                }
                g_seg[g] = lo;
            }
        }
    }
}

// ---------------- K2: degree histogram ----------------
__global__ void degree_kernel(const void* ei) {
    int e = blockIdx.x * blockDim.x + threadIdx.x;
    if (e < EE) {
        int r = fetch_idx(ei, e, g_flags[0]);
        atomicAdd(&g_deg[r], 1);
    }
}

// ---------------- K3: shuffle-based exclusive scan + dinv ----------------
__global__ void scan_dinv_kernel() {
    __shared__ int stot[32];
    int t = threadIdx.x;                  // 1024
    int lane = t & 31, wid = t >> 5;
    int base = t * 8;
    int d[8], loc[8];
    int run = 0;
#pragma unroll
    for (int k = 0; k < 8; k++) { d[k] = g_deg[base + k]; loc[k] = run; run += d[k]; }
    int v = run;
#pragma unroll
    for (int o = 1; o < 32; o <<= 1) {
        int n = __shfl_up_sync(0xffffffffu, v, o);
        if (lane >= o) v += n;
    }
    if (lane == 31) stot[wid] = v;
    __syncthreads();
    if (wid == 0) {
        int w = stot[lane];
#pragma unroll
        for (int o = 1; o < 32; o <<= 1) {
            int n = __shfl_up_sync(0xffffffffu, w, o);
            if (lane >= o) w += n;
        }
        stot[lane] = w;
    }
    __syncthreads();
    int warpoff = (wid > 0) ? stot[wid - 1] : 0;
    int excl = warpoff + v - run;
#pragma unroll
    for (int k = 0; k < 8; k++) {
        g_offs[base + k] = excl + loc[k];
        g_dinv[base + k] = (d[k] > 0) ? rsqrtf((float)d[k]) : 0.f;
    }
    if (t == 1023) g_offs[NN] = warpoff + v;
}

// ---------------- K4: scatter edges to CSR + copy x into Hcat[:,0:64] ----------------
// NOTE: grid must cover EE threads (R3 bug: grid sized only for the copy half).
__global__ void scatter_copy_kernel(const void* ei, const float* __restrict__ x) {
    int tid = blockIdx.x * blockDim.x + threadIdx.x;   // EE threads
    if (tid < EE) {
        int is32 = g_flags[0];
        int r = fetch_idx(ei, tid, is32);
        int c = fetch_idx(ei, (long long)EE + tid, is32);
        int pos = g_offs[r] + atomicAdd(&g_cnt[r], 1);
        g_col[pos] = c;
    }
    if (tid < NN * INC / 4) {               // 131072 float4 copies
        int row = tid >> 4, c4 = tid & 15;
        float4 v = ((const float4*)x)[tid];
        *(float4*)(g_Hcat + (long)row * DIN + c4 * 4) = v;
    }
}

// ---------------- K5/K6: SpMM  out = (I - D^-1/2 A D^-1/2) @ in ----------------
__global__ void spmm_kernel(const float* __restrict__ in, int ldin,
                            float* __restrict__ out, int ldout) {
    int gtid = blockIdx.x * blockDim.x + threadIdx.x;
    int node = gtid >> 5;
    int lane = gtid & 31;
    if (node >= NN) return;
    float di = g_dinv[node];
    int p = g_offs[node];
    int pe = g_offs[node + 1];
    float acc0 = 0.f, acc1 = 0.f;
    for (; p + 4 <= pe; p += 4) {
        int c0 = g_col[p], c1 = g_col[p + 1], c2 = g_col[p + 2], c3 = g_col[p + 3];
        float w0 = g_dinv[c0], w1 = g_dinv[c1], w2 = g_dinv[c2], w3 = g_dinv[c3];
        const float* r0 = in + (long)c0 * ldin;
        const float* r1 = in + (long)c1 * ldin;
        const float* r2 = in + (long)c2 * ldin;
        const float* r3 = in + (long)c3 * ldin;
        acc0 += w0 * r0[lane] + w1 * r1[lane] + w2 * r2[lane] + w3 * r3[lane];
        acc1 += w0 * r0[lane + 32] + w1 * r1[lane + 32] + w2 * r2[lane + 32] + w3 * r3[lane + 32];
    }
    for (; p < pe; p++) {
        int c0 = g_col[p];
        float w0 = g_dinv[c0];
        const float* r0 = in + (long)c0 * ldin;
        acc0 += w0 * r0[lane];
        acc1 += w0 * r0[lane + 32];
    }
    const float* ri = in + (long)node * ldin;
    out[(long)node * ldout + lane]      = ri[lane]      - di * acc0;
    out[(long)node * ldout + lane + 32] = ri[lane + 32] - di * acc1;
}

// ---------------- K7: sigma (power-iter step) + masked/scaled weight ----------------
__global__ void sigma_wm_kernel(const float* __restrict__ W, const float* __restrict__ u) {
    __shared__ float v[DIN];
    __shared__ float wsum[6];
    __shared__ float scal;
    __shared__ float invsig;
    int t = threadIdx.x;                  // 192
    int lane = t & 31, wid = t >> 5;
    float vt = 0.f;
    for (int i = 0; i < DOUT; i++) vt += W[i * DIN + t] * u[i];
    float w = vt * vt;
#pragma unroll
    for (int o = 16; o > 0; o >>= 1) w += __shfl_xor_sync(0xffffffffu, w, o);
    if (lane == 0) wsum[wid] = w;
    __syncthreads();
    if (t == 0) {
        float s2 = 0.f;
        for (int k = 0; k < 6; k++) s2 += wsum[k];
        scal = sqrtf(s2) + 1e-12f;
    }
    __syncthreads();
    v[t] = vt / scal;
    __syncthreads();
    float wv = 0.f;
    for (int j = 0; j < DIN; j++) wv += W[t * DIN + j] * v[j];
    float p = u[t] * wv;
#pragma unroll
    for (int o = 16; o > 0; o >>= 1) p += __shfl_xor_sync(0xffffffffu, p, o);
    if (lane == 0) wsum[wid] = p;
    __syncthreads();
    if (t == 0) {
        float sg = 0.f;
        for (int k = 0; k < 6; k++) sg += wsum[k];
        invsig = 1.0f / sg;
    }
    __syncthreads();
    float is = invsig;
    int kmax = INC * (t / OUTC + 1);
    const float* wr = W + (long)t * DIN;
    float* wo = g_Wm + (long)t * DIN;
    for (int c = 0; c < DIN; c++) wo[c] = (c < kmax) ? wr[c] * is : 0.f;
}

// ---------------- K8: GEMM H = Hcat @ Wm^T + b, K limited per n-tile, fused BN1 stats ----------------
__global__ void gemm_kernel(const float* __restrict__ bias) {
    __shared__ float As[16][65];
    __shared__ float Bs[16][65];
    __shared__ float ssum[16][68];
    __shared__ float ssq[16][68];
    int t  = threadIdx.x;                 // 256
    int tx = t & 15, ty = t >> 4;
    int m0 = blockIdx.x * 64;
    int n0 = blockIdx.y * 64;
    int kmax = 64 * (blockIdx.y + 1);     // block-lower-triangular mask
    int lm = t >> 2;
    int lk = (t & 3) * 4;
    float cr[4][4];
#pragma unroll
    for (int i = 0; i < 4; i++)
#pragma unroll
        for (int j = 0; j < 4; j++) cr[i][j] = 0.f;

    for (int k0 = 0; k0 < kmax; k0 += 16) {
        float4 av = *(const float4*)(g_Hcat + (long)(m0 + lm) * DIN + k0 + lk);
        As[lk + 0][lm] = av.x; As[lk + 1][lm] = av.y; As[lk + 2][lm] = av.z; As[lk + 3][lm] = av.w;
        float4 bv = *(const float4*)(g_Wm + (long)(n0 + lm) * DIN + k0 + lk);
        Bs[lk + 0][lm] = bv.x; Bs[lk + 1][lm] = bv.y; Bs[lk + 2][lm] = bv.z; Bs[lk + 3][lm] = bv.w;
        __syncthreads();
#pragma unroll
        for (int kk = 0; kk < 16; kk++) {
            float a0 = As[kk][ty * 4 + 0], a1 = As[kk][ty * 4 + 1];
            float a2 = As[kk][ty * 4 + 2], a3 = As[kk][ty * 4 + 3];
            float b0 = Bs[kk][tx * 4 + 0], b1 = Bs[kk][tx * 4 + 1];
            float b2 = Bs[kk][tx * 4 + 2], b3 = Bs[kk][tx * 4 + 3];
            cr[0][0] += a0 * b0; cr[0][1] += a0 * b1; cr[0][2] += a0 * b2; cr[0][3] += a0 * b3;
            cr[1][0] += a1 * b0; cr[1][1] += a1 * b1; cr[1][2] += a1 * b2; cr[1][3] += a1 * b3;
            cr[2][0] += a2 * b0; cr[2][1] += a2 * b1; cr[2][2] += a2 * b2; cr[2][3] += a2 * b3;
            cr[3][0] += a3 * b0; cr[3][1] += a3 * b1; cr[3][2] += a3 * b2; cr[3][3] += a3 * b3;
        }
        __syncthreads();
    }
    float psum[4], psq[4];
#pragma unroll
    for (int j = 0; j < 4; j++) { psum[j] = 0.f; psq[j] = 0.f; }
#pragma unroll
    for (int j = 0; j < 4; j++) {
        int n = n0 + tx * 4 + j;
        float bj = bias[n];
#pragma unroll
        for (int i = 0; i < 4; i++) {
            int m = m0 + ty * 4 + i;
            float v = cr[i][j] + bj;
            g_H[(long)m * DOUT + n] = v;
            psum[j] += v; psq[j] += v * v;
        }
    }
#pragma unroll
    for (int j = 0; j < 4; j++) { ssum[ty][tx * 4 + j] = psum[j]; ssq[ty][tx * 4 + j] = psq[j]; }
    __syncthreads();
    if (t < 64) {
        float s = 0.f, q = 0.f;
#pragma unroll
        for (int yy = 0; yy < 16; yy++) { s += ssum[yy][t]; q += ssq[yy][t]; }
        atomicAdd(&g_bnsum[n0 + t], s);
        atomicAdd(&g_bnsq[n0 + t], q);
    }
}

// ---------------- K9: BN1 apply + triple pooling (avg|sum|max) ----------------
__global__ void pool_kernel(const float* __restrict__ gamma, const float* __restrict__ beta) {
    __shared__ float sa[DOUT], sc[DOUT];
    __shared__ float psum[4][DOUT], pmax[4][DOUT];
    int g = blockIdx.x;
    int j = threadIdx.x;                  // 192
    int y = threadIdx.y;                  // 4
    if (y == 0) {
        float mu = g_bnsum[j] * (1.f / NN);
        float var = g_bnsq[j] * (1.f / NN) - mu * mu;
        float a = gamma[j] * rsqrtf(var + BNEPS);
        sa[j] = a;
        sc[j] = beta[j] - a * mu;
    }
    __syncthreads();
    int s = g_seg[g], e = g_seg[g + 1];
    float a = sa[j], c = sc[j];
    float sum = 0.f, mx = -INFINITY;
    for (int r = s + y; r < e; r += 4) {
        float v = a * g_H[(long)r * DOUT + j] + c;
        sum += v;
        mx = fmaxf(mx, v);
    }
    psum[y][j] = sum; pmax[y][j] = mx;
    __syncthreads();
    if (y == 0) {
        float ts = psum[0][j] + psum[1][j] + psum[2][j] + psum[3][j];
        float tm = fmaxf(fmaxf(pmax[0][j], pmax[1][j]), fmaxf(pmax[2][j], pmax[3][j]));
        float cnt = fmaxf((float)(e - s), 1.f);
        g_Hg[g * D3 + j]            = ts / cnt;
        g_Hg[g * D3 + DOUT + j]     = ts;
        g_Hg[g * D3 + 2 * DOUT + j] = tm;
    }
}

// ---------------- K10: head — BN2 + FC1(relu) + FC2(relu) + FC3 + log_softmax ----------------
__global__ void head_kernel(const float* __restrict__ g2, const float* __restrict__ be2,
                            const float* __restrict__ w1, const float* __restrict__ b1,
                            const float* __restrict__ w2, const float* __restrict__ b2,
                            const float* __restrict__ w3, const float* __restrict__ b3,
                            float* __restrict__ out) {
    __shared__ float xr[D3];
    __shared__ float f1[D2];
    __shared__ float f2[DOUT];
    int g = blockIdx.x;
    int t = threadIdx.x;                  // 384
    for (int ch = t; ch < D3; ch += D2) {
        float s = 0.f, q = 0.f;
#pragma unroll 4
        for (int r = 0; r < GG; r++) {
            float v = g_Hg[r * D3 + ch];
            s += v; q += v * v;
        }
        float mu = s * (1.f / GG);
        float var = q * (1.f / GG) - mu * mu;
        float a = g2[ch] * rsqrtf(var + BNEPS);
        xr[ch] = a * (g_Hg[g * D3 + ch] - mu) + be2[ch];
    }
    __syncthreads();
    {
        float acc = b1[t];
        const float* wr = w1 + (long)t * D3;
#pragma unroll 4
        for (int k = 0; k < D3; k++) acc += xr[k] * wr[k];
        f1[t] = fmaxf(acc, 0.f);
    }
    __syncthreads();
    if (t < DOUT) {
        float acc = b2[t];
        const float* wr = w2 + (long)t * D2;
#pragma unroll 4
        for (int k = 0; k < D2; k++) acc += f1[k] * wr[k];
        f2[t] = fmaxf(acc, 0.f);
    }
    __syncthreads();
    if (t < 32) {
        float logit = -INFINITY;
        if (t < NC) {
            float acc = b3[t];
            const float* wr = w3 + t * DOUT;
            for (int k = 0; k < DOUT; k++) acc += f2[k] * wr[k];
            logit = acc;
        }
        float mx = logit;
#pragma unroll
        for (int o = 16; o > 0; o >>= 1) mx = fmaxf(mx, __shfl_xor_sync(0xffffffffu, mx, o));
        float ex = (t < NC) ? expf(logit - mx) : 0.f;
        float se = ex;
#pragma unroll
        for (int o = 16; o > 0; o >>= 1) se += __shfl_xor_sync(0xffffffffu, se, o);
        if (t < NC) out[g * NC + t] = logit - mx - logf(se);
    }
}

// ---------------- launch ----------------
extern "C" void kernel_launch(void* const* d_in, const int* in_sizes, int n_in,
                              void* d_out, int out_size) {
    const float* x      = (const float*)d_in[0];
    const void*  ei     = d_in[1];
    const void*  batch  = d_in[2];
    const float* W_orig = (const float*)d_in[3];
    const float* b      = (const float*)d_in[4];
    const float* u      = (const float*)d_in[5];
    const float* bn1g   = (const float*)d_in[6];
    const float* bn1b   = (const float*)d_in[7];
    const float* bn2g   = (const float*)d_in[8];
    const float* bn2b   = (const float*)d_in[9];
    const float* w1     = (const float*)d_in[10];
    const float* b1     = (const float*)d_in[11];
    const float* w2     = (const float*)d_in[12];
    const float* b2     = (const float*)d_in[13];
    const float* w3     = (const float*)d_in[14];
    const float* b3     = (const float*)d_in[15];
    float* out = (float*)d_out;

    float* hcat_dev = nullptr;
    cudaGetSymbolAddress((void**)&hcat_dev, g_Hcat);

    init_kernel<<<64, 256>>>(ei, batch);
    degree_kernel<<<EE / 256, 256>>>(ei);
    scan_dinv_kernel<<<1, 1024>>>();
    scatter_copy_kernel<<<EE / 256, 256>>>(ei, x);   // FIXED: cover all EE edges
    spmm_kernel<<<NN * 32 / 256, 256>>>(x, INC, hcat_dev + INC, DIN);
    spmm_kernel<<<NN * 32 / 256, 256>>>(hcat_dev + INC, DIN, hcat_dev + 2 * INC, DIN);
    sigma_wm_kernel<<<1, DOUT>>>(W_orig, u);
    dim3 ggrid(NN / 64, DOUT / 64);
    gemm_kernel<<<ggrid, 256>>>(b);
    pool_kernel<<<GG, dim3(DOUT, 4)>>>(bn1g, bn1b);
    head_kernel<<<GG, D2>>>(bn2g, bn2b, w1, b1, w2, b2, w3, b3, out);
}